// round 15
// baseline (speedup 1.0000x reference)
#include <cuda_runtime.h>
#include <cuda_fp16.h>

#define MFERNS 8
#define KBITS 12
#define DOUT 32
#define NIMG 64
#define CCH 8
#define HIMG 128
#define WIMG 128
#define HP 120
#define WP 120
#define HOUT 114
#define WOUT 114
#define TROWS 4096
#define Y8 8
#define BLK 512
#define VS 122          // votes tile row stride (floats)
#define HPAD 116        // h row length in halves (114 valid + 2 pad)
#define XROWS 16        // staged x rows per channel (Y8 + 8)
#define PXB (Y8 * WP)   // 960 pixels per block
#define PXH 480         // pixels per half (thread q handles q and q+480)

// fp16 voting table: 8*4096*32 halves = 2 MB
__device__ uint2 g_table16[MFERNS * TROWS * DOUT / 4];

// fp16 horizontal-sum scratch: h[n][d][y][116] halves as uint2
__device__ uint2 g_h2[(size_t)NIMG * DOUT * HP * (HPAD / 4)];

// ---------------------------------------------------------------------------
// Kernel 0: convert table fp32 -> fp16
// ---------------------------------------------------------------------------
__global__ __launch_bounds__(256)
void cvt_kernel(const float* __restrict__ table)
{
    int i = blockIdx.x * 256 + threadIdx.x;
    float4 v = __ldg((const float4*)table + i);
    __half2 h0 = __floats2half2_rn(v.x, v.y);
    __half2 h1 = __floats2half2_rn(v.z, v.w);
    uint2 r;
    r.x = *(unsigned*)&h0;
    r.y = *(unsigned*)&h1;
    g_table16[i] = r;
}

// empty kernel for ncu stream-index alignment (profiled idx ≡ 3 mod 6 = votes)
__global__ void noop_kernel() {}

// ---------------------------------------------------------------------------
// Kernel 1: 8 y-rows per block, 512 threads, 2 blocks/SM (32 warps/SM).
//  Phase A: thread q computes pixels q and q+480 (descriptor LDS amortized 2x)
//  Phase B+H: run twice on 4-row chunks (votes tile reuses x-tile union)
// ---------------------------------------------------------------------------
__global__ __launch_bounds__(BLK, 2)
void votes_kernel(const float* __restrict__ x,
                  const float* __restrict__ thr,
                  const int* __restrict__ chan_idx,
                  const int* __restrict__ offsets)
{
    extern __shared__ float s_un[];           // union: x tile (16384 f) / votes tile (15632 f)
    __shared__ unsigned s_wc[MFERNS * PXB];   // packed conf|word, [m][pixel]
    __shared__ uint4    s_ot[96];             // {o1, o2, -14.427*thr bits, 0}

    const int tid = threadIdx.x;
    const int y0  = blockIdx.x * Y8;
    const int n   = blockIdx.y;

    if (tid < 96) {
        int c1 = chan_idx[2 * tid + 0];
        int c2 = chan_idx[2 * tid + 1];
        int dy1 = offsets[4 * tid + 0];
        int dx1 = offsets[4 * tid + 1];
        int dy2 = offsets[4 * tid + 2];
        int dx2 = offsets[4 * tid + 3];
        uint4 ot;
        ot.x = (unsigned)(c1 * (XROWS * 128) + dy1 * 128 + dx1);
        ot.y = (unsigned)(c2 * (XROWS * 128) + dy2 * 128 + dx2);
        float th14 = -14.4269504089f * thr[tid];   // (1/TEMP)*log2(e)*(-thr)
        ot.z = *(unsigned*)&th14;
        ot.w = 0;
        s_ot[tid] = ot;
    }

    // ---- stage x tile: 8 ch x 16 rows x 32 float4 = 4096 float4 ----
    {
        const float4* xs = (const float4*)x;
        float4* st = (float4*)s_un;
        for (int i = tid; i < CCH * XROWS * 32; i += BLK) {
            int c = i >> 9;              // 512 float4 per channel
            int r = i & 511;
            st[i] = __ldg(xs + (size_t)(n * CCH + c) * 4096 + y0 * 32 + r);
        }
    }
    __syncthreads();

    // ---- Phase A: 2 pixels per thread (q and q+480) ----
    {
        const int q = tid;
        if (q < PXH) {
            const int yl = q / WP;
            const int px = q - yl * WP;
            const int tb = yl * 128 + px;        // pixel q ; pixel q+480 at tb+512
#pragma unroll 1
            for (int m = 0; m < MFERNS; m++) {
                unsigned w0 = 0, w1 = 0;
                float d0 = 1.0f, d1 = 1.0f;
#pragma unroll
                for (int kp = 0; kp < KBITS / 2; kp++) {
                    uint4 otA = s_ot[m * KBITS + 2 * kp + 0];
                    uint4 otB = s_ot[m * KBITS + 2 * kp + 1];
                    const float* pA1 = s_un + otA.x + tb;
                    const float* pA2 = s_un + otA.y + tb;
                    const float* pB1 = s_un + otB.x + tb;
                    const float* pB2 = s_un + otB.y + tb;
                    float zA0 = fmaf(pA1[0]   - pA2[0],   14.4269504089f, __uint_as_float(otA.z));
                    float zA1 = fmaf(pA1[512] - pA2[512], 14.4269504089f, __uint_as_float(otA.z));
                    float zB0 = fmaf(pB1[0]   - pB2[0],   14.4269504089f, __uint_as_float(otB.z));
                    float zB1 = fmaf(pB1[512] - pB2[512], 14.4269504089f, __uint_as_float(otB.z));
                    if (zA0 > 0.0f) w0 |= (1u << (2 * kp));
                    if (zB0 > 0.0f) w0 |= (2u << (2 * kp));
                    if (zA1 > 0.0f) w1 |= (1u << (2 * kp));
                    if (zB1 > 0.0f) w1 |= (2u << (2 * kp));
                    // pair bit A across the two pixels, likewise bit B
                    __half2 hA = __floats2half2_rn(fminf(zA0, -zA0), fminf(zA1, -zA1));
                    __half2 hB = __floats2half2_rn(fminf(zB0, -zB0), fminf(zB1, -zB1));
                    unsigned eA, eB;
                    asm("ex2.approx.f16x2 %0, %1;" : "=r"(eA) : "r"(*(unsigned*)&hA));
                    asm("ex2.approx.f16x2 %0, %1;" : "=r"(eB) : "r"(*(unsigned*)&hB));
                    float2 fA = __half22float2(*(__half2*)&eA);
                    float2 fB = __half22float2(*(__half2*)&eB);
                    d0 = fmaf(d0, fA.x, d0);
                    d1 = fmaf(d1, fA.y, d1);
                    d0 = fmaf(d0, fB.x, d0);
                    d1 = fmaf(d1, fB.y, d1);
                }
                unsigned hb0 = (unsigned)__half_as_ushort(__float2half_rn(__frcp_rn(d0)));
                unsigned hb1 = (unsigned)__half_as_ushort(__float2half_rn(__frcp_rn(d1)));
                s_wc[m * PXB + q]       = (hb0 << 16) | w0;
                s_wc[m * PXB + PXH + q] = (hb1 << 16) | w1;
            }
        }
    }
    __syncthreads();

    const int warp = tid >> 5;           // 0..15
    const int lane = tid & 31;
    const int dq   = lane & 7;
    const int pin  = lane >> 3;

    // ---- two chunks of 4 rows: phase B (gather) then phase H (h-sum) ----
#pragma unroll 1
    for (int c = 0; c < 2; c++) {
        // Phase B: cooperative table gather -> fp32 smem votes tile [128][VS]
#pragma unroll 2
        for (int pass = 0; pass < 8; pass++) {
            int g = pass * 16 + warp;             // pixel group 0..127
            if (g < PXH / 4) {
                int lp = g * 4 + pin;             // local pixel 0..479
                int pid = c * PXH + lp;
                unsigned p_[MFERNS];
                uint2 t_[MFERNS];
#pragma unroll
                for (int m = 0; m < MFERNS; m++)
                    p_[m] = s_wc[m * PXB + pid];
#pragma unroll
                for (int m = 0; m < MFERNS; m++)
                    t_[m] = __ldg(&g_table16[((size_t)(m * TROWS) + (p_[m] & 0xFFFu)) * 8 + dq]);

                float a0 = 0.f, a1 = 0.f, a2 = 0.f, a3 = 0.f;
#pragma unroll
                for (int m = 0; m < MFERNS; m++) {
                    float cf = __half2float(__ushort_as_half((unsigned short)(p_[m] >> 16)));
                    float2 f0 = __half22float2(*(__half2*)&t_[m].x);
                    float2 f1 = __half22float2(*(__half2*)&t_[m].y);
                    a0 = fmaf(cf, f0.x, a0);
                    a1 = fmaf(cf, f0.y, a1);
                    a2 = fmaf(cf, f1.x, a2);
                    a3 = fmaf(cf, f1.y, a3);
                }
                int yl2 = lp / WP;
                int px2 = lp - yl2 * WP;
                float* vp = s_un + (yl2 * DOUT + dq * 4) * VS + px2;
                vp[0]      = a0;
                vp[VS]     = a1;
                vp[2 * VS] = a2;
                vp[3 * VS] = a3;
            }
        }
        __syncthreads();

        // Phase H: horizontal 7-sum -> fp16 h
        if (lane < 29) {
#pragma unroll 1
            for (int r = warp; r < 4 * DOUT; r += 16) {
                int yl2 = r >> 5;
                int d   = r & 31;
                const float* row = s_un + r * VS + 4 * lane;
                float2 q0 = *(const float2*)(row + 0);
                float2 q1 = *(const float2*)(row + 2);
                float2 q2 = *(const float2*)(row + 4);
                float2 q3 = *(const float2*)(row + 6);
                float2 q4 = *(const float2*)(row + 8);
                float s36 = q1.y + q2.x + q2.y + q3.x;
                float hx = q0.x + q0.y + q1.x + s36;
                float hy = q0.y + q1.x + s36 + q3.y;
                float hz = q1.x + s36 + q3.y + q4.x;
                float hw = s36 + q3.y + q4.x + q4.y;
                __half2 p0 = __floats2half2_rn(hx, hy);
                __half2 p1 = __floats2half2_rn(hz, hw);
                uint2 st;
                st.x = *(unsigned*)&p0;
                st.y = *(unsigned*)&p1;
                g_h2[((size_t)(n * DOUT + d) * HP + y0 + c * 4 + yl2) * (HPAD / 4) + lane] = st;
            }
        }
        __syncthreads();
    }
}

// ---------------------------------------------------------------------------
// Kernel 2: vertical 7-sum over fp16 h -> out[n][d][Y][X]
// ---------------------------------------------------------------------------
__global__ __launch_bounds__(256)
void pool_kernel(float* __restrict__ out)
{
    const int warp = threadIdx.x >> 5;
    const int lane = threadIdx.x & 31;
    if (lane > 28) return;

    const int gw = blockIdx.x * 8 + warp;
    const int h = gw & 1;
    const int nd = gw >> 1;
    const int y0 = h * 57;

    const uint2* ph = g_h2 + ((size_t)nd * HP + y0) * (HPAD / 4) + lane;
    float* po = out + (size_t)nd * (HOUT * WOUT) + (size_t)y0 * WOUT + 4 * lane;

    const float inv49 = 1.0f / 49.0f;
    float4 ring[7];
    float4 vs = make_float4(0.f, 0.f, 0.f, 0.f);

#pragma unroll
    for (int s = 0; s < 7; s++) {
        uint2 v = __ldg(ph + s * (HPAD / 4));
        float2 f0 = __half22float2(*(__half2*)&v.x);
        float2 f1 = __half22float2(*(__half2*)&v.y);
        float4 hh = make_float4(f0.x, f0.y, f1.x, f1.y);
        ring[s] = hh;
        vs.x += hh.x; vs.y += hh.y; vs.z += hh.z; vs.w += hh.w;
    }
    {
        *(float2*)po = make_float2(vs.x * inv49, vs.y * inv49);
        if (lane < 28)
            *(float2*)(po + 2) = make_float2(vs.z * inv49, vs.w * inv49);
    }

#pragma unroll 1
    for (int j = 1; j < 9; j++) {
#pragma unroll
        for (int s = 0; s < 7; s++) {
            int i = 7 * j + s;
            uint2 v = __ldg(ph + i * (HPAD / 4));
            float2 f0 = __half22float2(*(__half2*)&v.x);
            float2 f1 = __half22float2(*(__half2*)&v.y);
            float4 hh = make_float4(f0.x, f0.y, f1.x, f1.y);
            vs.x += hh.x - ring[s].x;
            vs.y += hh.y - ring[s].y;
            vs.z += hh.z - ring[s].z;
            vs.w += hh.w - ring[s].w;
            ring[s] = hh;
            float* op = po + (size_t)(i - 6) * WOUT;
            *(float2*)op = make_float2(vs.x * inv49, vs.y * inv49);
            if (lane < 28)
                *(float2*)(op + 2) = make_float2(vs.z * inv49, vs.w * inv49);
        }
    }
}

// ---------------------------------------------------------------------------
extern "C" void kernel_launch(void* const* d_in, const int* in_sizes, int n_in,
                              void* d_out, int out_size)
{
    const float* x        = (const float*)d_in[0];
    const float* thr      = (const float*)d_in[1];
    const float* table    = (const float*)d_in[2];
    const int*   chan_idx = (const int*)d_in[3];
    const int*   offsets  = (const int*)d_in[4];
    float* out = (float*)d_out;

    // union: max(x tile 16384 f, votes tile 4*32*VS+16 = 15632 f) = 16384 f
    const int dyn_smem = CCH * XROWS * 128 * 4;   // 65536 B
    cudaFuncSetAttribute(votes_kernel,
                         cudaFuncAttributeMaxDynamicSharedMemorySize, dyn_smem);

    // kernel stream (period 6): cvt(0) noop(1) noop(2) votes(3) pool(4) noop(5)
    cvt_kernel<<<1024, 256>>>(table);
    noop_kernel<<<1, 32>>>();
    noop_kernel<<<1, 32>>>();

    dim3 g1(HP / Y8, NIMG);
    votes_kernel<<<g1, BLK, dyn_smem>>>(x, thr, chan_idx, offsets);

    pool_kernel<<<512, 256>>>(out);
    noop_kernel<<<1, 32>>>();
}

// round 16
// speedup vs baseline: 1.5607x; 1.5607x over previous
#include <cuda_runtime.h>
#include <cuda_fp16.h>

#define MFERNS 8
#define KBITS 12
#define DOUT 32
#define NIMG 64
#define CCH 8
#define HIMG 128
#define WIMG 128
#define HP 120
#define WP 120
#define HOUT 114
#define WOUT 114
#define TROWS 4096
#define Y6 6
#define BLK 384
#define VS 122          // votes tile row stride (floats)
#define HPAD 116        // h row length in halves (114 valid + 2 pad)
#define XROWS 14        // staged x rows per channel (Y6 + 8)
#define PXB (Y6 * WP)   // 720 pixels per block
#define PXH 360         // pixels per half (thread q handles q and q+360)

// fp16 voting table: 8*4096*32 halves = 2 MB
__device__ uint2 g_table16[MFERNS * TROWS * DOUT / 4];

// fp16 horizontal-sum scratch: h[n][d][y][116] halves as uint2
__device__ uint2 g_h2[(size_t)NIMG * DOUT * HP * (HPAD / 4)];

// ---------------------------------------------------------------------------
// Kernel 0: convert table fp32 -> fp16
// ---------------------------------------------------------------------------
__global__ __launch_bounds__(256)
void cvt_kernel(const float* __restrict__ table)
{
    int i = blockIdx.x * 256 + threadIdx.x;
    float4 v = __ldg((const float4*)table + i);
    __half2 h0 = __floats2half2_rn(v.x, v.y);
    __half2 h1 = __floats2half2_rn(v.z, v.w);
    uint2 r;
    r.x = *(unsigned*)&h0;
    r.y = *(unsigned*)&h1;
    g_table16[i] = r;
}

// ---------------------------------------------------------------------------
// Kernel 1: 6 y-rows per block, 384 threads, 2 blocks/SM.
//  Phase A: thread q computes pixels q and q+360; ferns unrolled x2 for ILP
//  Phase B+H: run twice on 3-row chunks (votes tile reuses x-tile union)
// ---------------------------------------------------------------------------
__global__ __launch_bounds__(BLK, 2)
void votes_kernel(const float* __restrict__ x,
                  const float* __restrict__ thr,
                  const int* __restrict__ chan_idx,
                  const int* __restrict__ offsets)
{
    extern __shared__ float s_un[];           // union: x tile (14336 f) / votes tile (11728 f)
    __shared__ unsigned s_wc[MFERNS * PXB];   // packed conf|word, [m][pixel]
    __shared__ uint4    s_ot[96];             // {o1, o2, -14.427*thr bits, 0}

    const int tid = threadIdx.x;
    const int y0  = blockIdx.x * Y6;
    const int n   = blockIdx.y;

    if (tid < 96) {
        int c1 = chan_idx[2 * tid + 0];
        int c2 = chan_idx[2 * tid + 1];
        int dy1 = offsets[4 * tid + 0];
        int dx1 = offsets[4 * tid + 1];
        int dy2 = offsets[4 * tid + 2];
        int dx2 = offsets[4 * tid + 3];
        uint4 ot;
        ot.x = (unsigned)(c1 * (XROWS * 128) + dy1 * 128 + dx1);
        ot.y = (unsigned)(c2 * (XROWS * 128) + dy2 * 128 + dx2);
        float th14 = -14.4269504089f * thr[tid];   // (1/TEMP)*log2(e)*(-thr)
        ot.z = *(unsigned*)&th14;
        ot.w = 0;
        s_ot[tid] = ot;
    }

    // ---- stage x tile: 8 ch x 14 rows x 32 float4 = 3584 float4 ----
    {
        const float4* xs = (const float4*)x;
        float4* st = (float4*)s_un;
        for (int i = tid; i < CCH * XROWS * 32; i += BLK) {
            int c = i / (XROWS * 32);
            int r = i - c * (XROWS * 32);
            st[i] = __ldg(xs + (size_t)(n * CCH + c) * 4096 + y0 * 32 + r);
        }
    }
    __syncthreads();

    // ---- Phase A: 2 pixels per thread (q and q+360), ferns unrolled x2 ----
    {
        const int q = tid;
        if (q < PXH) {
            const int yl = q / WP;
            const int px = q - yl * WP;
            const int tb = yl * 128 + px;        // pixel q ; pixel q+360 at tb+384
#pragma unroll 2
            for (int m = 0; m < MFERNS; m++) {
                unsigned w0 = 0, w1 = 0;
                float d0 = 1.0f, d1 = 1.0f;
#pragma unroll
                for (int kp = 0; kp < KBITS / 2; kp++) {
                    uint4 otA = s_ot[m * KBITS + 2 * kp + 0];
                    uint4 otB = s_ot[m * KBITS + 2 * kp + 1];
                    const float* pA1 = s_un + otA.x + tb;
                    const float* pA2 = s_un + otA.y + tb;
                    const float* pB1 = s_un + otB.x + tb;
                    const float* pB2 = s_un + otB.y + tb;
                    float zA0 = fmaf(pA1[0]   - pA2[0],   14.4269504089f, __uint_as_float(otA.z));
                    float zA1 = fmaf(pA1[384] - pA2[384], 14.4269504089f, __uint_as_float(otA.z));
                    float zB0 = fmaf(pB1[0]   - pB2[0],   14.4269504089f, __uint_as_float(otB.z));
                    float zB1 = fmaf(pB1[384] - pB2[384], 14.4269504089f, __uint_as_float(otB.z));
                    if (zA0 > 0.0f) w0 |= (1u << (2 * kp));
                    if (zB0 > 0.0f) w0 |= (2u << (2 * kp));
                    if (zA1 > 0.0f) w1 |= (1u << (2 * kp));
                    if (zB1 > 0.0f) w1 |= (2u << (2 * kp));
                    // pair bit A across the two pixels, likewise bit B
                    __half2 hA = __floats2half2_rn(fminf(zA0, -zA0), fminf(zA1, -zA1));
                    __half2 hB = __floats2half2_rn(fminf(zB0, -zB0), fminf(zB1, -zB1));
                    unsigned eA, eB;
                    asm("ex2.approx.f16x2 %0, %1;" : "=r"(eA) : "r"(*(unsigned*)&hA));
                    asm("ex2.approx.f16x2 %0, %1;" : "=r"(eB) : "r"(*(unsigned*)&hB));
                    float2 fA = __half22float2(*(__half2*)&eA);
                    float2 fB = __half22float2(*(__half2*)&eB);
                    d0 = fmaf(d0, fA.x, d0);
                    d1 = fmaf(d1, fA.y, d1);
                    d0 = fmaf(d0, fB.x, d0);
                    d1 = fmaf(d1, fB.y, d1);
                }
                unsigned hb0 = (unsigned)__half_as_ushort(__float2half_rn(__frcp_rn(d0)));
                unsigned hb1 = (unsigned)__half_as_ushort(__float2half_rn(__frcp_rn(d1)));
                s_wc[m * PXB + q]       = (hb0 << 16) | w0;
                s_wc[m * PXB + PXH + q] = (hb1 << 16) | w1;
            }
        }
    }
    __syncthreads();

    const int warp = tid >> 5;           // 0..11
    const int lane = tid & 31;
    const int dq   = lane & 7;
    const int pin  = lane >> 3;

    // ---- two chunks of 3 rows: phase B (gather) then phase H (h-sum) ----
#pragma unroll 1
    for (int c = 0; c < 2; c++) {
        // Phase B: cooperative table gather -> fp32 smem votes tile [96][VS]
#pragma unroll 2
        for (int pass = 0; pass < 8; pass++) {
            int g = pass * 12 + warp;             // pixel group 0..95
            if (g < PXH / 4) {
                int lp = g * 4 + pin;             // local pixel 0..359
                int pid = c * PXH + lp;
                unsigned p_[MFERNS];
                uint2 t_[MFERNS];
#pragma unroll
                for (int m = 0; m < MFERNS; m++)
                    p_[m] = s_wc[m * PXB + pid];
#pragma unroll
                for (int m = 0; m < MFERNS; m++)
                    t_[m] = __ldg(&g_table16[((size_t)(m * TROWS) + (p_[m] & 0xFFFu)) * 8 + dq]);

                float a0 = 0.f, a1 = 0.f, a2 = 0.f, a3 = 0.f;
#pragma unroll
                for (int m = 0; m < MFERNS; m++) {
                    float cf = __half2float(__ushort_as_half((unsigned short)(p_[m] >> 16)));
                    float2 f0 = __half22float2(*(__half2*)&t_[m].x);
                    float2 f1 = __half22float2(*(__half2*)&t_[m].y);
                    a0 = fmaf(cf, f0.x, a0);
                    a1 = fmaf(cf, f0.y, a1);
                    a2 = fmaf(cf, f1.x, a2);
                    a3 = fmaf(cf, f1.y, a3);
                }
                int yl2 = lp / WP;
                int px2 = lp - yl2 * WP;
                float* vp = s_un + (yl2 * DOUT + dq * 4) * VS + px2;
                vp[0]      = a0;
                vp[VS]     = a1;
                vp[2 * VS] = a2;
                vp[3 * VS] = a3;
            }
        }
        __syncthreads();

        // Phase H: horizontal 7-sum -> fp16 h
        if (lane < 29) {
#pragma unroll 1
            for (int r = warp; r < 3 * DOUT; r += 12) {
                int yl2 = r >> 5;
                int d   = r & 31;
                const float* row = s_un + r * VS + 4 * lane;
                float2 q0 = *(const float2*)(row + 0);
                float2 q1 = *(const float2*)(row + 2);
                float2 q2 = *(const float2*)(row + 4);
                float2 q3 = *(const float2*)(row + 6);
                float2 q4 = *(const float2*)(row + 8);
                float s36 = q1.y + q2.x + q2.y + q3.x;
                float hx = q0.x + q0.y + q1.x + s36;
                float hy = q0.y + q1.x + s36 + q3.y;
                float hz = q1.x + s36 + q3.y + q4.x;
                float hw = s36 + q3.y + q4.x + q4.y;
                __half2 p0 = __floats2half2_rn(hx, hy);
                __half2 p1 = __floats2half2_rn(hz, hw);
                uint2 st;
                st.x = *(unsigned*)&p0;
                st.y = *(unsigned*)&p1;
                g_h2[((size_t)(n * DOUT + d) * HP + y0 + c * 3 + yl2) * (HPAD / 4) + lane] = st;
            }
        }
        __syncthreads();
    }
}

// ---------------------------------------------------------------------------
// Kernel 2: vertical 7-sum over fp16 h -> out[n][d][Y][X]
// ---------------------------------------------------------------------------
__global__ __launch_bounds__(256)
void pool_kernel(float* __restrict__ out)
{
    const int warp = threadIdx.x >> 5;
    const int lane = threadIdx.x & 31;
    if (lane > 28) return;

    const int gw = blockIdx.x * 8 + warp;
    const int h = gw & 1;
    const int nd = gw >> 1;
    const int y0 = h * 57;

    const uint2* ph = g_h2 + ((size_t)nd * HP + y0) * (HPAD / 4) + lane;
    float* po = out + (size_t)nd * (HOUT * WOUT) + (size_t)y0 * WOUT + 4 * lane;

    const float inv49 = 1.0f / 49.0f;
    float4 ring[7];
    float4 vs = make_float4(0.f, 0.f, 0.f, 0.f);

#pragma unroll
    for (int s = 0; s < 7; s++) {
        uint2 v = __ldg(ph + s * (HPAD / 4));
        float2 f0 = __half22float2(*(__half2*)&v.x);
        float2 f1 = __half22float2(*(__half2*)&v.y);
        float4 hh = make_float4(f0.x, f0.y, f1.x, f1.y);
        ring[s] = hh;
        vs.x += hh.x; vs.y += hh.y; vs.z += hh.z; vs.w += hh.w;
    }
    {
        *(float2*)po = make_float2(vs.x * inv49, vs.y * inv49);
        if (lane < 28)
            *(float2*)(po + 2) = make_float2(vs.z * inv49, vs.w * inv49);
    }

#pragma unroll 1
    for (int j = 1; j < 9; j++) {
#pragma unroll
        for (int s = 0; s < 7; s++) {
            int i = 7 * j + s;
            uint2 v = __ldg(ph + i * (HPAD / 4));
            float2 f0 = __half22float2(*(__half2*)&v.x);
            float2 f1 = __half22float2(*(__half2*)&v.y);
            float4 hh = make_float4(f0.x, f0.y, f1.x, f1.y);
            vs.x += hh.x - ring[s].x;
            vs.y += hh.y - ring[s].y;
            vs.z += hh.z - ring[s].z;
            vs.w += hh.w - ring[s].w;
            ring[s] = hh;
            float* op = po + (size_t)(i - 6) * WOUT;
            *(float2*)op = make_float2(vs.x * inv49, vs.y * inv49);
            if (lane < 28)
                *(float2*)(op + 2) = make_float2(vs.z * inv49, vs.w * inv49);
        }
    }
}

// ---------------------------------------------------------------------------
extern "C" void kernel_launch(void* const* d_in, const int* in_sizes, int n_in,
                              void* d_out, int out_size)
{
    const float* x        = (const float*)d_in[0];
    const float* thr      = (const float*)d_in[1];
    const float* table    = (const float*)d_in[2];
    const int*   chan_idx = (const int*)d_in[3];
    const int*   offsets  = (const int*)d_in[4];
    float* out = (float*)d_out;

    // union: max(x tile 14336 f, votes tile 3*32*VS+16 = 11728 f) = 14336 f
    const int dyn_smem = CCH * XROWS * 128 * 4;   // 57344 B
    cudaFuncSetAttribute(votes_kernel,
                         cudaFuncAttributeMaxDynamicSharedMemorySize, dyn_smem);

    cvt_kernel<<<1024, 256>>>(table);

    dim3 g1(HP / Y6, NIMG);
    votes_kernel<<<g1, BLK, dyn_smem>>>(x, thr, chan_idx, offsets);

    pool_kernel<<<512, 256>>>(out);
}